// round 1
// baseline (speedup 1.0000x reference)
#include <cuda_runtime.h>
#include <cstdint>
#include <cstddef>

#define FULLMASK 0xffffffffu

constexpr int BSZ  = 32;
constexpr int LSEQ = 8192;
constexpr int DDIM = 64;
constexpr int HID  = 256;
constexpr int NTOK = BSZ * LSEQ;          // 262144
constexpr int MTILE  = 128;               // tokens per CTA tile (pass 1)
constexpr int NTILES = NTOK / MTILE;      // 2048
constexpr int TL = 128;                   // l-tile (pass 2)
constexpr int LR = 18;                    // l-values per thread (8 groups * 18 = 144 = TL + 12 halo + 4 pad)

// scratch (no cudaMalloc allowed)
__device__ float g_mu[(size_t)NTOK * DDIM];     // gated mu, 64 MB
__device__ float g_epart[BSZ * 64];             // per-tile energy partials

__device__ __forceinline__ uint32_t f2tf(float f) {
    uint32_t u; asm("cvt.rna.tf32.f32 %0, %1;" : "=r"(u) : "f"(f)); return u;
}

__device__ __forceinline__ void mma8(float c[4], const uint32_t a[4], uint2 b) {
    asm volatile(
        "mma.sync.aligned.m16n8k8.row.col.f32.tf32.tf32.f32 "
        "{%0,%1,%2,%3}, {%4,%5,%6,%7}, {%8,%9}, {%0,%1,%2,%3};"
        : "+f"(c[0]), "+f"(c[1]), "+f"(c[2]), "+f"(c[3])
        : "r"(a[0]), "r"(a[1]), "r"(a[2]), "r"(a[3]), "r"(b.x), "r"(b.y));
}

__device__ __forceinline__ float softplus_f(float v) {
    return fmaxf(v, 0.f) + log1pf(__expf(-fabsf(v)));
}

// ---------------------------------------------------------------------------
// Pass 1: mu[b,l,:] = softplus(relu([A,B]@W1+b1)@W2+b2) * (1 + 0.5*tanh(q@Wq+bq))
// tf32 mma.sync, fragment-packed weights in SMEM, persistent CTAs.
// Each warp owns 16 token rows; hidden C-frags are converted to A-frags via
// shuffles and consumed immediately by GEMM2 (no hidden staging).
// ---------------------------------------------------------------------------
__global__ __launch_bounds__(256, 1)
void mu_kernel(const float* __restrict__ A, const float* __restrict__ B,
               const float* __restrict__ q,
               const float* __restrict__ W1, const float* __restrict__ b1,
               const float* __restrict__ W2, const float* __restrict__ b2,
               const float* __restrict__ Wq, const float* __restrict__ bq)
{
    extern __shared__ uint32_t sm[];
    uint2* w1p = (uint2*)sm;                 // [16 kt][32 nt][32 lane] -> 128 KB
    uint2* w2p = w1p + 16 * 32 * 32;         // [32 kt][ 8 nt][32 lane] ->  64 KB
    uint2* wqp = w2p + 32 * 8 * 32;          // [ 8 kt][ 8 nt][32 lane] ->  16 KB
    float* b1s = (float*)(wqp + 8 * 8 * 32);
    float* b2s = b1s + 256;
    float* bqs = b2s + 64;

    const int tid = threadIdx.x;

    // ---- pack weights into mma B-fragment layout (once per CTA) ----
    for (int idx = tid; idx < 16 * 32 * 32; idx += 256) {
        int lane = idx & 31, nt = (idx >> 5) & 31, kt = idx >> 10;
        int k = kt * 8 + (lane & 3), n = nt * 8 + (lane >> 2);
        w1p[idx] = make_uint2(f2tf(W1[k * HID + n]), f2tf(W1[(k + 4) * HID + n]));
    }
    for (int idx = tid; idx < 32 * 8 * 32; idx += 256) {
        int lane = idx & 31, nt = (idx >> 5) & 7, kt = idx >> 8;
        int k = kt * 8 + (lane & 3), n = nt * 8 + (lane >> 2);
        w2p[idx] = make_uint2(f2tf(W2[k * DDIM + n]), f2tf(W2[(k + 4) * DDIM + n]));
    }
    for (int idx = tid; idx < 8 * 8 * 32; idx += 256) {
        int lane = idx & 31, nt = (idx >> 5) & 7, kt = idx >> 8;
        int k = kt * 8 + (lane & 3), n = nt * 8 + (lane >> 2);
        wqp[idx] = make_uint2(f2tf(Wq[k * DDIM + n]), f2tf(Wq[(k + 4) * DDIM + n]));
    }
    if (tid < 256) b1s[tid] = b1[tid];
    if (tid < 64)  b2s[tid] = b2[tid];
    if (tid < 64)  bqs[tid] = bq[tid];
    __syncthreads();

    const int wid = tid >> 5, lane = tid & 31;
    const int c4 = lane & 3, rq = lane >> 2;

    for (int tile = blockIdx.x; tile < NTILES; tile += gridDim.x) {
        const int r0 = tile * MTILE + wid * 16 + rq;   // rows r0 and r0+8

        // ---- A-operand: X = [A|B] rows, kept entirely in registers ----
        uint32_t xa[64];
        #pragma unroll
        for (int kt = 0; kt < 16; kt++) {
            const float* src = (kt < 8) ? A : B;
            int k = (kt & 7) * 8 + c4;
            size_t o0 = (size_t)r0 * DDIM + k;
            size_t o1 = o0 + (size_t)8 * DDIM;
            xa[kt * 4 + 0] = f2tf(__ldg(src + o0));
            xa[kt * 4 + 1] = f2tf(__ldg(src + o1));
            xa[kt * 4 + 2] = f2tf(__ldg(src + o0 + 4));
            xa[kt * 4 + 3] = f2tf(__ldg(src + o1 + 4));
        }

        // ---- gate GEMM: tanh(q @ Wq + bq) -> gacc holds (1 + 0.5*tanh) ----
        float gacc[32];
        #pragma unroll
        for (int i = 0; i < 32; i++) gacc[i] = 0.f;
        {
            uint32_t qa[32];
            #pragma unroll
            for (int kt = 0; kt < 8; kt++) {
                int k = kt * 8 + c4;
                size_t o0 = (size_t)r0 * DDIM + k;
                size_t o1 = o0 + (size_t)8 * DDIM;
                qa[kt * 4 + 0] = f2tf(__ldg(q + o0));
                qa[kt * 4 + 1] = f2tf(__ldg(q + o1));
                qa[kt * 4 + 2] = f2tf(__ldg(q + o0 + 4));
                qa[kt * 4 + 3] = f2tf(__ldg(q + o1 + 4));
            }
            #pragma unroll
            for (int kt = 0; kt < 8; kt++)
                #pragma unroll
                for (int nt = 0; nt < 8; nt++)
                    mma8(&gacc[nt * 4], &qa[kt * 4], wqp[(kt * 8 + nt) * 32 + lane]);
        }
        #pragma unroll
        for (int nt = 0; nt < 8; nt++) {
            int col0 = nt * 8 + 2 * c4;
            gacc[nt * 4 + 0] = 1.f + 0.5f * tanhf(gacc[nt * 4 + 0] + bqs[col0]);
            gacc[nt * 4 + 1] = 1.f + 0.5f * tanhf(gacc[nt * 4 + 1] + bqs[col0 + 1]);
            gacc[nt * 4 + 2] = 1.f + 0.5f * tanhf(gacc[nt * 4 + 2] + bqs[col0]);
            gacc[nt * 4 + 3] = 1.f + 0.5f * tanhf(gacc[nt * 4 + 3] + bqs[col0 + 1]);
        }

        // ---- fused GEMM1 (relu) -> GEMM2 over hidden chunks of 8 ----
        float oacc[32];
        #pragma unroll
        for (int i = 0; i < 32; i++) oacc[i] = 0.f;

        #pragma unroll 1
        for (int nc = 0; nc < 32; nc++) {
            float h[4] = {0.f, 0.f, 0.f, 0.f};
            #pragma unroll
            for (int kt = 0; kt < 16; kt++)
                mma8(h, &xa[kt * 4], w1p[(kt * 32 + nc) * 32 + lane]);

            int col0 = nc * 8 + 2 * c4;
            h[0] = fmaxf(h[0] + b1s[col0],     0.f);
            h[1] = fmaxf(h[1] + b1s[col0 + 1], 0.f);
            h[2] = fmaxf(h[2] + b1s[col0],     0.f);
            h[3] = fmaxf(h[3] + b1s[col0 + 1], 0.f);

            // C-fragment (m16n8) -> A-fragment (m16k8) via shuffles
            int srcA = (lane & ~3) | (c4 >> 1);
            int srcB = srcA + 2;
            float p00 = __shfl_sync(FULLMASK, h[0], srcA), p01 = __shfl_sync(FULLMASK, h[1], srcA);
            float p20 = __shfl_sync(FULLMASK, h[2], srcA), p21 = __shfl_sync(FULLMASK, h[3], srcA);
            float u00 = __shfl_sync(FULLMASK, h[0], srcB), u01 = __shfl_sync(FULLMASK, h[1], srcB);
            float u20 = __shfl_sync(FULLMASK, h[2], srcB), u21 = __shfl_sync(FULLMASK, h[3], srcB);
            bool odd = (c4 & 1);
            uint32_t ah[4];
            ah[0] = f2tf(odd ? p01 : p00);
            ah[1] = f2tf(odd ? p21 : p20);
            ah[2] = f2tf(odd ? u01 : u00);
            ah[3] = f2tf(odd ? u21 : u20);

            #pragma unroll
            for (int nt = 0; nt < 8; nt++)
                mma8(&oacc[nt * 4], ah, w2p[(nc * 8 + nt) * 32 + lane]);
        }

        // ---- finalize: softplus, gate, store gated mu ----
        float* mu0 = g_mu + (size_t)r0 * DDIM;
        float* mu1 = mu0 + (size_t)8 * DDIM;
        #pragma unroll
        for (int nt = 0; nt < 8; nt++) {
            int col0 = nt * 8 + 2 * c4;
            float s0 = softplus_f(oacc[nt * 4 + 0] + b2s[col0]);
            float s1 = softplus_f(oacc[nt * 4 + 1] + b2s[col0 + 1]);
            float s2 = softplus_f(oacc[nt * 4 + 2] + b2s[col0]);
            float s3 = softplus_f(oacc[nt * 4 + 3] + b2s[col0 + 1]);
            *(float2*)(mu0 + col0) = make_float2(s0 * gacc[nt * 4 + 0], s1 * gacc[nt * 4 + 1]);
            *(float2*)(mu1 + col0) = make_float2(s2 * gacc[nt * 4 + 2], s3 * gacc[nt * 4 + 3]);
        }
    }
}

// ---------------------------------------------------------------------------
// Pass 2: K=6 coupled smoothing in sum/difference form, register-resident.
//   s  <- smooth(s)           (s0 = A+B)
//   dd <- smooth((1-0.3*mu)*dd)   (dd0 = A-B)
// Tile of 128 l-rows + halo 6 per side, circular. Thread = (d, l-group of 18).
// Only segment-edge values cross threads (via tiny SMEM buffers).
// ---------------------------------------------------------------------------
__global__ __launch_bounds__(512, 1)
void stencil_kernel(const float* __restrict__ A, const float* __restrict__ B,
                    float* __restrict__ hA, float* __restrict__ hB)
{
    const int b    = blockIdx.x >> 6;
    const int tile = blockIdx.x & 63;
    const int l0   = tile * TL;
    const int tid  = threadIdx.x;
    const int d    = tid & 63, gq = tid >> 6;   // gq in [0,8)

    __shared__ float eD[2][8][64], eS[2][8][64];
    __shared__ float red[16];

    float mu[LR], dd[LR], ss[LR];
    const size_t base_b = (size_t)b * LSEQ * DDIM;

    #pragma unroll
    for (int j = 0; j < LR; j++) {
        int i = gq * LR + j;                      // local index 0..143
        int l = (l0 - 6 + i) & (LSEQ - 1);        // circular
        size_t o = base_b + (size_t)l * DDIM + d;
        float a = A[o], bb = B[o];
        mu[j] = g_mu[o];
        dd[j] = a - bb;
        ss[j] = a + bb;
    }

    for (int it = 0; it < 6; it++) {
        float td0 = fmaf(-0.3f, mu[0], 1.f) * dd[0];
        float tdL = fmaf(-0.3f, mu[LR - 1], 1.f) * dd[LR - 1];
        eD[0][gq][d] = td0;        eD[1][gq][d] = tdL;
        eS[0][gq][d] = ss[0];      eS[1][gq][d] = ss[LR - 1];
        __syncthreads();

        float prevD = (gq > 0) ? eD[1][gq - 1][d] : 0.f;
        float prevS = (gq > 0) ? eS[1][gq - 1][d] : 0.f;
        float edgeD = (gq < 7) ? eD[0][gq + 1][d] : 0.f;
        float edgeS = (gq < 7) ? eS[0][gq + 1][d] : 0.f;
        float curD = td0, curS = ss[0];

        #pragma unroll
        for (int j = 0; j < LR; j++) {
            float nxtD = (j < LR - 1) ? fmaf(-0.3f, mu[j + 1], 1.f) * dd[j + 1] : edgeD;
            float nxtS = (j < LR - 1) ? ss[j + 1] : edgeS;
            dd[j] = 0.9f * curD + 0.05f * (prevD + nxtD);
            ss[j] = 0.9f * curS + 0.05f * (prevS + nxtS);
            prevD = curD; prevS = curS;
            curD = nxtD;  curS = nxtS;
        }
        __syncthreads();
    }

    // write valid region [6, 6+TL) and accumulate energy
    float esum = 0.f;
    #pragma unroll
    for (int j = 0; j < LR; j++) {
        int i = gq * LR + j;
        if (i >= 6 && i < 6 + TL) {
            int l = l0 + (i - 6);
            size_t o = base_b + (size_t)l * DDIM + d;
            hA[o] = 0.5f * (ss[j] + dd[j]);
            hB[o] = 0.5f * (ss[j] - dd[j]);
            esum += 0.5f * mu[j] * dd[j] * dd[j];
        }
    }
    #pragma unroll
    for (int off = 16; off > 0; off >>= 1)
        esum += __shfl_down_sync(FULLMASK, esum, off);
    if ((tid & 31) == 0) red[tid >> 5] = esum;
    __syncthreads();
    if (tid == 0) {
        float s = 0.f;
        #pragma unroll
        for (int w = 0; w < 16; w++) s += red[w];
        g_epart[blockIdx.x] = s;
    }
}

// ---------------------------------------------------------------------------
// Pass 3: deterministic energy finalize (no atomics, no init needed)
// ---------------------------------------------------------------------------
__global__ void energy_kernel(float* __restrict__ en)
{
    __shared__ float sred[64];
    int b = blockIdx.x, t = threadIdx.x;
    sred[t] = g_epart[b * 64 + t];
    __syncthreads();
    if (t == 0) {
        float s = 0.f;
        #pragma unroll
        for (int i = 0; i < 64; i++) s += sred[i];
        en[b] = s;
    }
}

extern "C" void kernel_launch(void* const* d_in, const int* in_sizes, int n_in,
                              void* d_out, int out_size)
{
    const float* A  = (const float*)d_in[0];
    const float* B  = (const float*)d_in[1];
    const float* q  = (const float*)d_in[2];
    const float* W1 = (const float*)d_in[3];
    const float* b1 = (const float*)d_in[4];
    const float* W2 = (const float*)d_in[5];
    const float* b2 = (const float*)d_in[6];
    const float* Wq = (const float*)d_in[7];
    const float* bq = (const float*)d_in[8];

    float* hA = (float*)d_out;
    float* hB = hA + (size_t)NTOK * DDIM;
    float* en = hB + (size_t)NTOK * DDIM;

    const int smem_bytes = (16 * 32 * 32 + 32 * 8 * 32 + 8 * 8 * 32) * 8
                         + (256 + 64 + 64) * 4;   // 214528 B
    cudaFuncSetAttribute(mu_kernel, cudaFuncAttributeMaxDynamicSharedMemorySize, smem_bytes);

    mu_kernel<<<152, 256, smem_bytes>>>(A, B, q, W1, b1, W2, b2, Wq, bq);
    stencil_kernel<<<BSZ * 64, 512>>>(A, B, hA, hB);
    energy_kernel<<<BSZ, 64>>>(en);
}

// round 3
// speedup vs baseline: 1.1610x; 1.1610x over previous
#include <cuda_runtime.h>
#include <cstdint>
#include <cstddef>

#define FULLMASK 0xffffffffu

constexpr int BSZ  = 32;
constexpr int LSEQ = 8192;
constexpr int DDIM = 64;
constexpr int HID  = 256;
constexpr int NTOK = BSZ * LSEQ;          // 262144
constexpr int MTILE  = 128;               // tokens per CTA tile (pass 1)
constexpr int NTILES = NTOK / MTILE;      // 2048

// pass-2 geometry: TL=64 l-rows per CTA, 8 groups x 10 l-values (12 halo + 64 + 4 pad)
constexpr int TL2 = 64;
constexpr int G2  = 8;
constexpr int LR2 = 10;
constexpr int NT2 = 4096;                 // 32 b * 128 tiles

// scratch (no cudaMalloc allowed)
__device__ float g_mu[(size_t)NTOK * DDIM];     // gated mu, 64 MB
__device__ float g_epart[NT2];                  // per-tile energy partials

__device__ __forceinline__ uint32_t f2tf(float f) {
    uint32_t u; asm("cvt.rna.tf32.f32 %0, %1;" : "=r"(u) : "f"(f)); return u;
}

__device__ __forceinline__ void mma8(float c[4], const uint32_t a[4], uint2 b) {
    asm volatile(
        "mma.sync.aligned.m16n8k8.row.col.f32.tf32.tf32.f32 "
        "{%0,%1,%2,%3}, {%4,%5,%6,%7}, {%8,%9}, {%0,%1,%2,%3};"
        : "+f"(c[0]), "+f"(c[1]), "+f"(c[2]), "+f"(c[3])
        : "r"(a[0]), "r"(a[1]), "r"(a[2]), "r"(a[3]), "r"(b.x), "r"(b.y));
}

__device__ __forceinline__ float softplus_f(float v) {
    return fmaxf(v, 0.f) + log1pf(__expf(-fabsf(v)));
}

// ---------------------------------------------------------------------------
// Pass 1: mu = softplus(relu([A,B]@W1+b1)@W2+b2) * (1 + 0.5*tanh(q@Wq+bq))
// tf32 mma.sync, fragment-packed weights in SMEM, persistent CTAs.
// ILP: GEMM1 chain split into two 8-deep halves; nc loop unrolled x2 so
// 4 independent mma chains are in flight per warp (occupancy is smem-capped
// at 8 warps/SM, so registers are spent freely on ILP).
// ---------------------------------------------------------------------------
__global__ __launch_bounds__(256, 1)
void mu_kernel(const float* __restrict__ A, const float* __restrict__ B,
               const float* __restrict__ q,
               const float* __restrict__ W1, const float* __restrict__ b1,
               const float* __restrict__ W2, const float* __restrict__ b2,
               const float* __restrict__ Wq, const float* __restrict__ bq)
{
    extern __shared__ uint32_t sm[];
    uint2* w1p = (uint2*)sm;                 // [16 kt][32 nt][32 lane] -> 128 KB
    uint2* w2p = w1p + 16 * 32 * 32;         // [32 kt][ 8 nt][32 lane] ->  64 KB
    uint2* wqp = w2p + 32 * 8 * 32;          // [ 8 kt][ 8 nt][32 lane] ->  16 KB
    float* b1s = (float*)(wqp + 8 * 8 * 32);
    float* b2s = b1s + 256;
    float* bqs = b2s + 64;

    const int tid = threadIdx.x;

    // ---- pack weights into mma B-fragment layout (once per CTA) ----
    for (int idx = tid; idx < 16 * 32 * 32; idx += 256) {
        int lane = idx & 31, nt = (idx >> 5) & 31, kt = idx >> 10;
        int k = kt * 8 + (lane & 3), n = nt * 8 + (lane >> 2);
        w1p[idx] = make_uint2(f2tf(W1[k * HID + n]), f2tf(W1[(k + 4) * HID + n]));
    }
    for (int idx = tid; idx < 32 * 8 * 32; idx += 256) {
        int lane = idx & 31, nt = (idx >> 5) & 7, kt = idx >> 8;
        int k = kt * 8 + (lane & 3), n = nt * 8 + (lane >> 2);
        w2p[idx] = make_uint2(f2tf(W2[k * DDIM + n]), f2tf(W2[(k + 4) * DDIM + n]));
    }
    for (int idx = tid; idx < 8 * 8 * 32; idx += 256) {
        int lane = idx & 31, nt = (idx >> 5) & 7, kt = idx >> 8;
        int k = kt * 8 + (lane & 3), n = nt * 8 + (lane >> 2);
        wqp[idx] = make_uint2(f2tf(Wq[k * DDIM + n]), f2tf(Wq[(k + 4) * DDIM + n]));
    }
    if (tid < 256) b1s[tid] = b1[tid];
    if (tid < 64)  b2s[tid] = b2[tid];
    if (tid < 64)  bqs[tid] = bq[tid];
    __syncthreads();

    const int wid = tid >> 5, lane = tid & 31;
    const int c4 = lane & 3, rq = lane >> 2;

    for (int tile = blockIdx.x; tile < NTILES; tile += gridDim.x) {
        const int r0 = tile * MTILE + wid * 16 + rq;   // rows r0 and r0+8

        // ---- A-operand: X = [A|B] rows, kept entirely in registers ----
        uint32_t xa[64];
        #pragma unroll
        for (int kt = 0; kt < 16; kt++) {
            const float* src = (kt < 8) ? A : B;
            int k = (kt & 7) * 8 + c4;
            size_t o0 = (size_t)r0 * DDIM + k;
            size_t o1 = o0 + (size_t)8 * DDIM;
            xa[kt * 4 + 0] = f2tf(__ldg(src + o0));
            xa[kt * 4 + 1] = f2tf(__ldg(src + o1));
            xa[kt * 4 + 2] = f2tf(__ldg(src + o0 + 4));
            xa[kt * 4 + 3] = f2tf(__ldg(src + o1 + 4));
        }

        // ---- gate GEMM: gacc holds (1 + 0.5*tanh(q@Wq+bq)) ----
        float gacc[32];
        #pragma unroll
        for (int i = 0; i < 32; i++) gacc[i] = 0.f;
        {
            uint32_t qa[32];
            #pragma unroll
            for (int kt = 0; kt < 8; kt++) {
                int k = kt * 8 + c4;
                size_t o0 = (size_t)r0 * DDIM + k;
                size_t o1 = o0 + (size_t)8 * DDIM;
                qa[kt * 4 + 0] = f2tf(__ldg(q + o0));
                qa[kt * 4 + 1] = f2tf(__ldg(q + o1));
                qa[kt * 4 + 2] = f2tf(__ldg(q + o0 + 4));
                qa[kt * 4 + 3] = f2tf(__ldg(q + o1 + 4));
            }
            #pragma unroll
            for (int kt = 0; kt < 8; kt++)
                #pragma unroll
                for (int nt = 0; nt < 8; nt++)
                    mma8(&gacc[nt * 4], &qa[kt * 4], wqp[(kt * 8 + nt) * 32 + lane]);
        }
        #pragma unroll
        for (int nt = 0; nt < 8; nt++) {
            int col0 = nt * 8 + 2 * c4;
            gacc[nt * 4 + 0] = 1.f + 0.5f * tanhf(gacc[nt * 4 + 0] + bqs[col0]);
            gacc[nt * 4 + 1] = 1.f + 0.5f * tanhf(gacc[nt * 4 + 1] + bqs[col0 + 1]);
            gacc[nt * 4 + 2] = 1.f + 0.5f * tanhf(gacc[nt * 4 + 2] + bqs[col0]);
            gacc[nt * 4 + 3] = 1.f + 0.5f * tanhf(gacc[nt * 4 + 3] + bqs[col0 + 1]);
        }

        // ---- fused GEMM1 (relu) -> GEMM2 over hidden chunks of 8 ----
        float oacc[32];
        #pragma unroll
        for (int i = 0; i < 32; i++) oacc[i] = 0.f;

        #pragma unroll 2
        for (int nc = 0; nc < 32; nc++) {
            // two independent 8-deep accumulation chains (ILP)
            float h0[4] = {0.f, 0.f, 0.f, 0.f};
            float h1[4] = {0.f, 0.f, 0.f, 0.f};
            #pragma unroll
            for (int kt = 0; kt < 8; kt++) {
                mma8(h0, &xa[kt * 4],        w1p[(kt * 32 + nc) * 32 + lane]);
                mma8(h1, &xa[(kt + 8) * 4],  w1p[((kt + 8) * 32 + nc) * 32 + lane]);
            }

            int col0 = nc * 8 + 2 * c4;
            float h[4];
            h[0] = fmaxf(h0[0] + h1[0] + b1s[col0],     0.f);
            h[1] = fmaxf(h0[1] + h1[1] + b1s[col0 + 1], 0.f);
            h[2] = fmaxf(h0[2] + h1[2] + b1s[col0],     0.f);
            h[3] = fmaxf(h0[3] + h1[3] + b1s[col0 + 1], 0.f);

            // C-fragment (m16n8) -> A-fragment (m16k8) via shuffles
            int srcA = (lane & ~3) | (c4 >> 1);
            int srcB = srcA + 2;
            float p00 = __shfl_sync(FULLMASK, h[0], srcA), p01 = __shfl_sync(FULLMASK, h[1], srcA);
            float p20 = __shfl_sync(FULLMASK, h[2], srcA), p21 = __shfl_sync(FULLMASK, h[3], srcA);
            float u00 = __shfl_sync(FULLMASK, h[0], srcB), u01 = __shfl_sync(FULLMASK, h[1], srcB);
            float u20 = __shfl_sync(FULLMASK, h[2], srcB), u21 = __shfl_sync(FULLMASK, h[3], srcB);
            bool odd = (c4 & 1);
            uint32_t ah[4];
            ah[0] = f2tf(odd ? p01 : p00);
            ah[1] = f2tf(odd ? p21 : p20);
            ah[2] = f2tf(odd ? u01 : u00);
            ah[3] = f2tf(odd ? u21 : u20);

            #pragma unroll
            for (int nt = 0; nt < 8; nt++)
                mma8(&oacc[nt * 4], ah, w2p[(nc * 8 + nt) * 32 + lane]);
        }

        // ---- finalize: softplus, gate, store gated mu ----
        float* mu0 = g_mu + (size_t)r0 * DDIM;
        float* mu1 = mu0 + (size_t)8 * DDIM;
        #pragma unroll
        for (int nt = 0; nt < 8; nt++) {
            int col0 = nt * 8 + 2 * c4;
            float s0 = softplus_f(oacc[nt * 4 + 0] + b2s[col0]);
            float s1 = softplus_f(oacc[nt * 4 + 1] + b2s[col0 + 1]);
            float s2 = softplus_f(oacc[nt * 4 + 2] + b2s[col0]);
            float s3 = softplus_f(oacc[nt * 4 + 3] + b2s[col0 + 1]);
            *(float2*)(mu0 + col0) = make_float2(s0 * gacc[nt * 4 + 0], s1 * gacc[nt * 4 + 1]);
            *(float2*)(mu1 + col0) = make_float2(s2 * gacc[nt * 4 + 2], s3 * gacc[nt * 4 + 3]);
        }
    }
}

// ---------------------------------------------------------------------------
// Pass 2: K=6 coupled smoothing in sum/difference form, register-resident.
//   s  <- smooth(s)              (s0 = A+B)
//   dd <- smooth((1-0.3*mu)*dd)  (dd0 = A-B)
// TL2=64 l-rows per CTA (+6 halo each side), 512 threads = (d, group of 10).
// Low register count -> 2 CTAs/SM resident for latency overlap.
// ---------------------------------------------------------------------------
__global__ __launch_bounds__(512, 2)
void stencil_kernel(const float* __restrict__ A, const float* __restrict__ B,
                    float* __restrict__ hA, float* __restrict__ hB)
{
    const int b    = blockIdx.x >> 7;          // 128 tiles per batch row
    const int tile = blockIdx.x & 127;
    const int l0   = tile * TL2;
    const int tid  = threadIdx.x;
    const int d    = tid & 63, gq = tid >> 6;  // gq in [0,8)

    __shared__ float eD[2][G2][64], eS[2][G2][64];
    __shared__ float red[16];

    float mu[LR2], dd[LR2], ss[LR2];
    const size_t base_b = (size_t)b * LSEQ * DDIM;

    #pragma unroll
    for (int j = 0; j < LR2; j++) {
        int i = gq * LR2 + j;                     // local index 0..79
        int l = (l0 - 6 + i) & (LSEQ - 1);        // circular
        size_t o = base_b + (size_t)l * DDIM + d;
        float a = A[o], bb = B[o];
        mu[j] = g_mu[o];
        dd[j] = a - bb;
        ss[j] = a + bb;
    }

    for (int it = 0; it < 6; it++) {
        float td0 = fmaf(-0.3f, mu[0], 1.f) * dd[0];
        float tdL = fmaf(-0.3f, mu[LR2 - 1], 1.f) * dd[LR2 - 1];
        eD[0][gq][d] = td0;        eD[1][gq][d] = tdL;
        eS[0][gq][d] = ss[0];      eS[1][gq][d] = ss[LR2 - 1];
        __syncthreads();

        float prevD = (gq > 0) ? eD[1][gq - 1][d] : 0.f;
        float prevS = (gq > 0) ? eS[1][gq - 1][d] : 0.f;
        float edgeD = (gq < G2 - 1) ? eD[0][gq + 1][d] : 0.f;
        float edgeS = (gq < G2 - 1) ? eS[0][gq + 1][d] : 0.f;
        float curD = td0, curS = ss[0];

        #pragma unroll
        for (int j = 0; j < LR2; j++) {
            float nxtD = (j < LR2 - 1) ? fmaf(-0.3f, mu[j + 1], 1.f) * dd[j + 1] : edgeD;
            float nxtS = (j < LR2 - 1) ? ss[j + 1] : edgeS;
            dd[j] = 0.9f * curD + 0.05f * (prevD + nxtD);
            ss[j] = 0.9f * curS + 0.05f * (prevS + nxtS);
            prevD = curD; prevS = curS;
            curD = nxtD;  curS = nxtS;
        }
        __syncthreads();
    }

    // write valid region [6, 6+TL2) and accumulate energy
    float esum = 0.f;
    #pragma unroll
    for (int j = 0; j < LR2; j++) {
        int i = gq * LR2 + j;
        if (i >= 6 && i < 6 + TL2) {
            int l = l0 + (i - 6);
            size_t o = base_b + (size_t)l * DDIM + d;
            hA[o] = 0.5f * (ss[j] + dd[j]);
            hB[o] = 0.5f * (ss[j] - dd[j]);
            esum += 0.5f * mu[j] * dd[j] * dd[j];
        }
    }
    #pragma unroll
    for (int off = 16; off > 0; off >>= 1)
        esum += __shfl_down_sync(FULLMASK, esum, off);
    if ((tid & 31) == 0) red[tid >> 5] = esum;
    __syncthreads();
    if (tid == 0) {
        float s = 0.f;
        #pragma unroll
        for (int w = 0; w < 16; w++) s += red[w];
        g_epart[blockIdx.x] = s;
    }
}

// ---------------------------------------------------------------------------
// Pass 3: deterministic energy finalize (no atomics, no init needed)
// ---------------------------------------------------------------------------
__global__ void energy_kernel(float* __restrict__ en)
{
    __shared__ float sred[128];
    int b = blockIdx.x, t = threadIdx.x;
    sred[t] = g_epart[b * 128 + t];
    __syncthreads();
    if (t == 0) {
        float s = 0.f;
        #pragma unroll
        for (int i = 0; i < 128; i++) s += sred[i];
        en[b] = s;
    }
}

extern "C" void kernel_launch(void* const* d_in, const int* in_sizes, int n_in,
                              void* d_out, int out_size)
{
    const float* A  = (const float*)d_in[0];
    const float* B  = (const float*)d_in[1];
    const float* q  = (const float*)d_in[2];
    const float* W1 = (const float*)d_in[3];
    const float* b1 = (const float*)d_in[4];
    const float* W2 = (const float*)d_in[5];
    const float* b2 = (const float*)d_in[6];
    const float* Wq = (const float*)d_in[7];
    const float* bq = (const float*)d_in[8];

    float* hA = (float*)d_out;
    float* hB = hA + (size_t)NTOK * DDIM;
    float* en = hB + (size_t)NTOK * DDIM;

    const int smem_bytes = (16 * 32 * 32 + 32 * 8 * 32 + 8 * 8 * 32) * 8
                         + (256 + 64 + 64) * 4;   // 214528 B
    cudaFuncSetAttribute(mu_kernel, cudaFuncAttributeMaxDynamicSharedMemorySize, smem_bytes);

    mu_kernel<<<152, 256, smem_bytes>>>(A, B, q, W1, b1, W2, b2, Wq, bq);
    stencil_kernel<<<NT2, 512>>>(A, B, hA, hB);
    energy_kernel<<<BSZ, 128>>>(en);
}